// round 16
// baseline (speedup 1.0000x reference)
#include <cuda_runtime.h>
#include <cuda_fp16.h>
#include <math.h>
#include <stdint.h>

#define NN   262144
#define NG   2048
#define DX   256
#define DG   128
#define HID  256
#define BN_EPS 1e-3f
#define MTILE 64
#define NCTA (NN / MTILE)
#define NTHR 256

// ---- smem byte map (108,800 B per CTA; 2 CTAs/SM) ----
// B ring: 4 slots x 16KB @ 0 (pair p occupies slots {0,1} if p even else {2,3})
#define ABUF   65536    // A quad-buf (GEMM1, overlays h1): slice s @ +(s%4)*9216
#define H1     65536    // h1 [64 m][256 k] fp16, 512B rows, XOR (r&7)<<4 ; 32KB
#define P_S0   102400
#define P_SH0  103424
#define P_S1   104448
#define P_SH1  105472
#define P_W2   106496
#define SIDX   107520   // 256B
#define PART   107776   // 1KB float[4][64]
#define SMEM_TOTAL 108800

__device__ float g_norm[NG];
__device__ float gHGF[NG * HID];          // per-graph gf @ W0g  (fp32, L2-resident)
// fragment-major fp16 weight images, 16KB per 32-k chunk:
// u32 index = c*4096 + ks*2048 + nw*512 + jp*128 + lane*4 + r
__device__ __align__(16) uint16_t gW0[8 * 8192];   // x-part of W0 only (k<256)
__device__ __align__(16) uint16_t gW1[8 * 8192];

// ======================= helpers =======================
__device__ __forceinline__ uint32_t smem_u32(const void* p) {
    uint32_t a;
    asm("{ .reg .u64 t; cvta.to.shared.u64 t, %1; cvt.u32.u64 %0, t; }"
        : "=r"(a) : "l"(p));
    return a;
}
__device__ __forceinline__ void cp16(uint32_t dst, const void* src) {
    asm volatile("cp.async.cg.shared.global [%0], [%1], 16;"
                 :: "r"(dst), "l"(__cvta_generic_to_global(src)) : "memory");
}
#define CP_COMMIT() asm volatile("cp.async.commit_group;" ::: "memory")
#define CP_WAIT0()  asm volatile("cp.async.wait_group 0;" ::: "memory")
#define CP_WAIT1()  asm volatile("cp.async.wait_group 1;" ::: "memory")

__device__ __forceinline__ void mma16816h(float* c, const uint32_t* a,
                                          uint32_t b0, uint32_t b1) {
    asm volatile(
        "mma.sync.aligned.m16n8k16.row.col.f32.f16.f16.f32 "
        "{%0,%1,%2,%3}, {%4,%5,%6,%7}, {%8,%9}, {%0,%1,%2,%3};"
        : "+f"(c[0]), "+f"(c[1]), "+f"(c[2]), "+f"(c[3])
        : "r"(a[0]), "r"(a[1]), "r"(a[2]), "r"(a[3]), "r"(b0), "r"(b1));
}
__device__ __forceinline__ void ldsm4(uint32_t* d, uint32_t addr) {
    asm volatile("ldmatrix.sync.aligned.m8n8.x4.shared.b16 {%0,%1,%2,%3}, [%4];"
                 : "=r"(d[0]), "=r"(d[1]), "=r"(d[2]), "=r"(d[3]) : "r"(addr));
}
__device__ __forceinline__ uint32_t pack2h(float a, float b) {
    __half2 h = __floats2half2_rn(a, b);
    return *(uint32_t*)&h;
}

// ======================= small kernels =======================
// Per-graph: hgf[g][n] = sum_k gf[g][k] * W0[256+k][n]  (fp32, 8 graphs/block)
// Also zeroes g_norm (thread<8 of each block).
__global__ void prep_hgf_kernel(const float* __restrict__ gf,
                                const float* __restrict__ W0) {
    __shared__ float sg[8][DG];
    int n = threadIdx.x;
    int g0 = blockIdx.x * 8;
    if (n < 8) g_norm[g0 + n] = 0.0f;
    for (int i = n; i < 8 * DG; i += 256)
        sg[i >> 7][i & 127] = gf[(size_t)g0 * DG + i];
    __syncthreads();
    float acc[8] = {0.f, 0.f, 0.f, 0.f, 0.f, 0.f, 0.f, 0.f};
    for (int k = 0; k < DG; k++) {
        float w = W0[(size_t)(DX + k) * HID + n];
        #pragma unroll
        for (int p = 0; p < 8; p++) acc[p] = fmaf(sg[p][k], w, acc[p]);
    }
    #pragma unroll
    for (int p = 0; p < 8; p++) gHGF[(size_t)(g0 + p) * HID + n] = acc[p];
}

// W:[K,256] row-major -> fragment-major fp16 image (same layout as R9)
__global__ void prep_w_kernel(const float* __restrict__ W, uint32_t* __restrict__ dst) {
    int idx = blockIdx.x * 256 + threadIdx.x;
    int c    = idx >> 12;
    int ks   = (idx >> 11) & 1;
    int nw   = (idx >> 9) & 3;
    int jp   = (idx >> 7) & 3;
    int lane = (idx >> 2) & 31;
    int r    = idx & 3;
    int j = jp * 2 + (r >> 1);
    int n = nw * 64 + j * 8 + (lane >> 2);
    int kg = c * 32 + ks * 16 + 2 * (lane & 3) + 8 * (r & 1);
    uint32_t lo = __half_as_ushort(__float2half(W[(size_t)kg * 256 + n]));
    uint32_t hi = __half_as_ushort(__float2half(W[(size_t)(kg + 1) * 256 + n]));
    dst[idx] = lo | (hi << 16);
}

__global__ void norm_kernel(const int* __restrict__ bidx, float* __restrict__ out) {
    int i = blockIdx.x * 256 + threadIdx.x;
    out[i] = out[i] / g_norm[bidx[i]];
}

// ======================= device sub-steps =======================
// cp.async one 32KB weight PAIR (2 chunks) into slots {0,1} or {2,3}
// pair 0..3 -> gW0 chunks 2p,2p+1 ; pair 4..7 -> gW1 chunks 2(p-4),2(p-4)+1
__device__ __forceinline__ void issueB2(uint32_t sb, int pair, int tid) {
    const uint16_t* src = (pair < 4) ? (gW0 + pair * 16384)
                                     : (gW1 + (pair - 4) * 16384);
    uint32_t d = sb + (uint32_t)(pair & 1) * 32768u;
    #pragma unroll
    for (int i = tid; i < 2048; i += NTHR)
        cp16(d + i * 16, (const char*)src + i * 16);
}

// A 32k-slice load: 64 rows x 32 k fp32 -> 2 float4 per thread
__device__ __forceinline__ void ldgA(int c, const float* x, int row0, int tid,
                                     float4& f0, float4& f1) {
    int r = tid >> 2, q = tid & 3;
    const float* src = x + (size_t)(row0 + r) * DX + c * 32 + q * 8;
    f0 = *(const float4*)src;
    f1 = *((const float4*)src + 1);
}

// fp16-convert 8 floats -> single STS.128 into A slice buf (s%4), 144B rows
__device__ __forceinline__ void stsA(char* smc, int s, float4 f0, float4 f1, int tid) {
    int r = tid >> 2, q = tid & 3;
    uint32_t off = ABUF + (uint32_t)(s & 3) * 9216u + (uint32_t)(r * 144 + q * 16);
    *(uint4*)(smc + off) = make_uint4(pack2h(f0.x, f0.y), pack2h(f0.z, f0.w),
                                      pack2h(f1.x, f1.y), pack2h(f1.z, f1.w));
}

// ======================= main fused kernel =======================
__global__ __launch_bounds__(NTHR, 2) void att_kernel(
    const float* __restrict__ x, const int* __restrict__ bidx,
    const float* __restrict__ b0,
    const float* __restrict__ W2, const float* __restrict__ b2,
    const float* __restrict__ gamma0, const float* __restrict__ beta0,
    const float* __restrict__ mean0, const float* __restrict__ var0,
    const float* __restrict__ b1,
    const float* __restrict__ gamma1, const float* __restrict__ beta1,
    const float* __restrict__ mean1, const float* __restrict__ var1,
    float* __restrict__ out)
{
    extern __shared__ char smc[];
    const uint32_t sb = smem_u32(smc);
    const int tid = threadIdx.x;
    const int wid = tid >> 5;
    const int lane = tid & 31;
    const int row0 = blockIdx.x * MTILE;
    const int mw = wid >> 2;          // 0..1  M groups of 32
    const int nw = wid & 3;           // 0..3  N groups of 64
    const int qr = lane >> 2;         // 0..7
    const int l15 = lane & 15;
    const int lk  = (lane >> 4) << 4;

    int* sidx = (int*)(smc + SIDX);
    if (tid < MTILE) sidx[tid] = bidx[row0 + tid];
    {   // fold BN params (256 threads = 256 cols)
        int cc = tid;
        float s0v = gamma0[cc] * rsqrtf(var0[cc] + BN_EPS);
        ((float*)(smc + P_S0))[cc]  = s0v;
        ((float*)(smc + P_SH0))[cc] = fmaf(b0[cc] - mean0[cc], s0v, beta0[cc]);
        float s1v = gamma1[cc] * rsqrtf(var1[cc] + BN_EPS);
        ((float*)(smc + P_S1))[cc]  = s1v;
        ((float*)(smc + P_SH1))[cc] = fmaf(b1[cc] - mean1[cc], s1v, beta1[cc]);
        ((float*)(smc + P_W2))[cc]  = W2[cc];
    }

    // prologue: stage W0 pairs 0,1 ; convert A slices 0,1
    issueB2(sb, 0, tid); CP_COMMIT();
    issueB2(sb, 1, tid); CP_COMMIT();
    {
        float4 f0, f1;
        ldgA(0, x, row0, tid, f0, f1); stsA(smc, 0, f0, f1, tid);
        ldgA(1, x, row0, tid, f0, f1); stsA(smc, 1, f0, f1, tid);
    }
    CP_WAIT1();          // pair 0 landed (pending {1})
    __syncthreads();     // pair 0 + A(0,1) + params visible

    float C[2][8][4];
    #pragma unroll
    for (int m = 0; m < 2; m++)
        #pragma unroll
        for (int j = 0; j < 8; j++)
            #pragma unroll
            for (int p = 0; p < 4; p++) C[m][j][p] = 0.0f;

    const uint32_t bfrag = (uint32_t)(nw * 2048 + lane * 16);

    // =================== GEMM1: [64 x 256] @ W0x (4 pairs of 32k chunks) ===================
    // Invariant at top of pair p: pair p landed + visible; A slices 2p,2p+1 visible.
    for (int p = 0; p < 4; p++) {
        const uint32_t pairBase = (uint32_t)(p & 1) * 32768u;
        const bool more = (p < 3);
        float4 fA0, fA1;

        #pragma unroll
        for (int h = 0; h < 2; h++) {
            const int s = 2 * p + h;           // slice index 0..7
            if (more) ldgA(s + 2, x, row0, tid, fA0, fA1);
            {   // MMA slice s: B at pairBase + h*16384, A at abuf s%4
                const uint32_t bsoff = pairBase + (uint32_t)h * 16384u;
                const uint32_t ab = sb + ABUF + (uint32_t)(s & 3) * 9216u;
                #pragma unroll
                for (int ks = 0; ks < 2; ks++) {
                    uint32_t a[2][4];
                    #pragma unroll
                    for (int m = 0; m < 2; m++)
                        ldsm4(a[m], ab + (uint32_t)((mw * 32 + m * 16 + l15) * 144 + ks * 32) + lk);
                    #pragma unroll
                    for (int jp = 0; jp < 4; jp++) {
                        uint4 bv = *(const uint4*)(smc + bsoff + ks * 8192 + bfrag + jp * 512);
                        mma16816h(C[0][jp * 2],     a[0], bv.x, bv.y);
                        mma16816h(C[0][jp * 2 + 1], a[0], bv.z, bv.w);
                        mma16816h(C[1][jp * 2],     a[1], bv.x, bv.y);
                        mma16816h(C[1][jp * 2 + 1], a[1], bv.z, bv.w);
                    }
                }
            }
            if (more) stsA(smc, s + 2, fA0, fA1, tid);
        }

        __syncthreads();                 // ALL reads of pair p + A bufs done (WAR close)
        issueB2(sb, p + 2, tid);         // safe: slots of pair p no longer read
        CP_COMMIT();                     // pending {p+1, p+2}
        CP_WAIT1();                      // pair p+1 landed (pending {p+2})
        __syncthreads();                 // pair p+1 + A(2p+2,2p+3) visible (RAW close)
    }

    // ====== Epilogue 1: add per-graph hgf, BN0+ReLU, fp16 convert, write h1 ======
    // (invariant after loop: pair 4 = W1 c0/c1 landed + visible; ABUF reads all done)
    {
        const float* sS0  = (const float*)(smc + P_S0);
        const float* sSH0 = (const float*)(smc + P_SH0);
        #pragma unroll
        for (int m = 0; m < 2; m++) {
            int r = mw * 32 + m * 16 + qr;
            const float2* hgA = (const float2*)(gHGF + (size_t)sidx[r] * HID);
            const float2* hgB = (const float2*)(gHGF + (size_t)sidx[r + 8] * HID);
            uint32_t xr0 = (uint32_t)(qr << 4);
            uint32_t rb0 = (uint32_t)(r * 512);
            uint32_t rb1 = (uint32_t)((r + 8) * 512);
            #pragma unroll
            for (int j = 0; j < 8; j++) {
                int col = nw * 64 + j * 8 + (lane & 3) * 2;
                float2 ha = hgA[col >> 1];
                float2 hb = hgB[col >> 1];
                float s0a = sS0[col], s0b = sS0[col + 1];
                float h0a = sSH0[col], h0b = sSH0[col + 1];
                float v00 = fmaxf(fmaf(C[m][j][0] + ha.x, s0a, h0a), 0.f);
                float v01 = fmaxf(fmaf(C[m][j][1] + ha.y, s0b, h0b), 0.f);
                float v10 = fmaxf(fmaf(C[m][j][2] + hb.x, s0a, h0a), 0.f);
                float v11 = fmaxf(fmaf(C[m][j][3] + hb.y, s0b, h0b), 0.f);
                uint32_t ko = ((uint32_t)(col * 2)) ^ xr0;
                *(uint32_t*)(smc + H1 + rb0 + ko) = pack2h(v00, v01);
                *(uint32_t*)(smc + H1 + rb1 + ko) = pack2h(v10, v11);
            }
        }
    }
    __syncthreads();     // h1 visible

    #pragma unroll
    for (int m = 0; m < 2; m++)
        #pragma unroll
        for (int j = 0; j < 8; j++)
            #pragma unroll
            for (int p = 0; p < 4; p++) C[m][j][p] = 0.0f;

    // =================== GEMM2: h1 [64 x 256] @ W1 (4 pairs) ===================
    // Invariant at top of q: pair 4+q landed + visible.
    for (int q = 0; q < 4; q++) {
        const uint32_t pairBase = (uint32_t)((4 + q) & 1) * 32768u;
        #pragma unroll
        for (int h = 0; h < 2; h++) {
            const int ci = 2 * q + h;          // W1 chunk 0..7
            const uint32_t bsoff = pairBase + (uint32_t)h * 16384u;
            #pragma unroll
            for (int ks = 0; ks < 2; ks++) {
                uint32_t a[2][4];
                #pragma unroll
                for (int m = 0; m < 2; m++) {
                    int row = mw * 32 + m * 16 + l15;
                    uint32_t kb = (uint32_t)(ci * 64 + ks * 32) + (uint32_t)lk;
                    ldsm4(a[m], sb + H1 + (uint32_t)(row * 512) +
                                 (kb ^ ((uint32_t)(row & 7) << 4)));
                }
                #pragma unroll
                for (int jp = 0; jp < 4; jp++) {
                    uint4 bv = *(const uint4*)(smc + bsoff + ks * 8192 + bfrag + jp * 512);
                    mma16816h(C[0][jp * 2],     a[0], bv.x, bv.y);
                    mma16816h(C[0][jp * 2 + 1], a[0], bv.z, bv.w);
                    mma16816h(C[1][jp * 2],     a[1], bv.x, bv.y);
                    mma16816h(C[1][jp * 2 + 1], a[1], bv.z, bv.w);
                }
            }
        }
        if (q < 3) {
            __syncthreads();                   // reads of pair 4+q done (WAR close)
            if (q < 2) { issueB2(sb, 6 + q, tid); CP_COMMIT(); CP_WAIT1(); }
            else       { CP_WAIT0(); }         // q==2: drain pair 7 (nothing newer)
            __syncthreads();                   // pair 5+q visible (RAW close)
        }
    }

    // ====== Epilogue 2: BN1+ReLU, dot W2, reduce, exp, segment atomics ======
    {
        const float* sS1  = (const float*)(smc + P_S1);
        const float* sSH1 = (const float*)(smc + P_SH1);
        const float* sW2  = (const float*)(smc + P_W2);
        float pl[2][2] = {{0.f, 0.f}, {0.f, 0.f}};
        #pragma unroll
        for (int m = 0; m < 2; m++) {
            #pragma unroll
            for (int j = 0; j < 8; j++) {
                int col = nw * 64 + j * 8 + (lane & 3) * 2;
                float s1a = sS1[col], s1b = sS1[col + 1];
                float h1a = sSH1[col], h1b = sSH1[col + 1];
                float w2a = sW2[col], w2b = sW2[col + 1];
                pl[m][0] = fmaf(fmaxf(fmaf(C[m][j][0], s1a, h1a), 0.f), w2a, pl[m][0]);
                pl[m][0] = fmaf(fmaxf(fmaf(C[m][j][1], s1b, h1b), 0.f), w2b, pl[m][0]);
                pl[m][1] = fmaf(fmaxf(fmaf(C[m][j][2], s1a, h1a), 0.f), w2a, pl[m][1]);
                pl[m][1] = fmaf(fmaxf(fmaf(C[m][j][3], s1b, h1b), 0.f), w2b, pl[m][1]);
            }
        }
        #pragma unroll
        for (int off = 1; off <= 2; off <<= 1)
            #pragma unroll
            for (int m = 0; m < 2; m++) {
                pl[m][0] += __shfl_xor_sync(0xffffffffu, pl[m][0], off);
                pl[m][1] += __shfl_xor_sync(0xffffffffu, pl[m][1], off);
            }
        float* part = (float*)(smc + PART);
        if ((lane & 3) == 0) {
            #pragma unroll
            for (int m = 0; m < 2; m++) {
                int r = mw * 32 + m * 16 + qr;
                part[nw * 64 + r]     = pl[m][0];
                part[nw * 64 + r + 8] = pl[m][1];
            }
        }
        __syncthreads();
        if (tid < MTILE) {
            float logit = part[tid] + part[64 + tid] + part[128 + tid] +
                          part[192 + tid] + b2[0];
            float av = expf(logit);
            out[row0 + tid] = av;
            atomicAdd(&g_norm[sidx[tid]], av);
        }
    }
}

// ======================= launch =======================
extern "C" void kernel_launch(void* const* d_in, const int* in_sizes, int n_in,
                              void* d_out, int out_size) {
    const float* x      = (const float*)d_in[0];
    const int*   bidx   = (const int*)  d_in[1];
    const float* gf     = (const float*)d_in[2];
    const float* W0     = (const float*)d_in[3];
    const float* b0     = (const float*)d_in[4];
    const float* W1     = (const float*)d_in[5];
    const float* b1     = (const float*)d_in[6];
    const float* W2     = (const float*)d_in[7];
    const float* b2     = (const float*)d_in[8];
    const float* gamma0 = (const float*)d_in[9];
    const float* beta0  = (const float*)d_in[10];
    const float* mean0  = (const float*)d_in[11];
    const float* var0   = (const float*)d_in[12];
    const float* gamma1 = (const float*)d_in[13];
    const float* beta1  = (const float*)d_in[14];
    const float* mean1  = (const float*)d_in[15];
    const float* var1   = (const float*)d_in[16];
    float* out = (float*)d_out;

    static uint32_t *pW0 = nullptr, *pW1;
    if (!pW0) {
        cudaGetSymbolAddress((void**)&pW0, gW0);
        cudaGetSymbolAddress((void**)&pW1, gW1);
        cudaFuncSetAttribute(att_kernel, cudaFuncAttributeMaxDynamicSharedMemorySize,
                             SMEM_TOTAL);
    }

    prep_w_kernel<<<128, 256>>>(W0, pW0);    // 8 chunks (k<256 of W0)
    prep_w_kernel<<<128, 256>>>(W1, pW1);    // 8 chunks
    prep_hgf_kernel<<<NG / 8, 256>>>(gf, W0);  // also zeroes g_norm
    att_kernel<<<NCTA, NTHR, SMEM_TOTAL>>>(
        x, bidx, b0, W2, b2,
        gamma0, beta0, mean0, var0,
        b1, gamma1, beta1, mean1, var1, out);
    norm_kernel<<<NN / 256, 256>>>(bidx, out);
}

// round 17
// speedup vs baseline: 1.0871x; 1.0871x over previous
#include <cuda_runtime.h>
#include <cuda_fp16.h>
#include <math.h>
#include <stdint.h>

#define NN   262144
#define NG   2048
#define DX   256
#define DG   128
#define HID  256
#define BN_EPS 1e-3f
#define MTILE 64
#define NCTA (NN / MTILE)
#define NTHR 256

// ---- smem byte map (88,320 B per CTA; 2 CTAs/SM) ----
// B stages: slot s @ s*16384 (3 slots, 16KB fragment-major chunk each)
#define ABUF   49152    // A dbl-buf (GEMM1, overlays h1): buf p @ +p*9216, 64 rows x 144B
#define H1     49152    // h1 [64 m][256 k] fp16, 512B rows, XOR (r&7)<<4 ; 32KB
#define P_S0   81920
#define P_SH0  82944
#define P_S1   83968
#define P_SH1  84992
#define P_W2   86016
#define SIDX   87040    // 256B
#define PART   87296    // 1KB float[4][64]
#define SMEM_TOTAL 88320

__device__ float g_norm[NG];
__device__ float gHGF[NG * HID];          // per-graph gf @ W0g  (fp32, L2-resident)
// fragment-major fp16 weight images, 16KB per 32-k chunk:
// u32 index = c*4096 + ks*2048 + nw*512 + jp*128 + lane*4 + r
__device__ __align__(16) uint16_t gW0[8 * 8192];   // x-part of W0 only (k<256)
__device__ __align__(16) uint16_t gW1[8 * 8192];

// ======================= helpers =======================
__device__ __forceinline__ uint32_t smem_u32(const void* p) {
    uint32_t a;
    asm("{ .reg .u64 t; cvta.to.shared.u64 t, %1; cvt.u32.u64 %0, t; }"
        : "=r"(a) : "l"(p));
    return a;
}
__device__ __forceinline__ void cp16(uint32_t dst, const void* src) {
    asm volatile("cp.async.cg.shared.global [%0], [%1], 16;"
                 :: "r"(dst), "l"(__cvta_generic_to_global(src)) : "memory");
}
#define CP_COMMIT() asm volatile("cp.async.commit_group;" ::: "memory")
#define CP_WAIT0()  asm volatile("cp.async.wait_group 0;" ::: "memory")
#define CP_WAIT1()  asm volatile("cp.async.wait_group 1;" ::: "memory")

__device__ __forceinline__ void mma16816h(float* c, const uint32_t* a,
                                          uint32_t b0, uint32_t b1) {
    asm volatile(
        "mma.sync.aligned.m16n8k16.row.col.f32.f16.f16.f32 "
        "{%0,%1,%2,%3}, {%4,%5,%6,%7}, {%8,%9}, {%0,%1,%2,%3};"
        : "+f"(c[0]), "+f"(c[1]), "+f"(c[2]), "+f"(c[3])
        : "r"(a[0]), "r"(a[1]), "r"(a[2]), "r"(a[3]), "r"(b0), "r"(b1));
}
__device__ __forceinline__ void ldsm4(uint32_t* d, uint32_t addr) {
    asm volatile("ldmatrix.sync.aligned.m8n8.x4.shared.b16 {%0,%1,%2,%3}, [%4];"
                 : "=r"(d[0]), "=r"(d[1]), "=r"(d[2]), "=r"(d[3]) : "r"(addr));
}
__device__ __forceinline__ uint32_t pack2h(float a, float b) {
    __half2 h = __floats2half2_rn(a, b);
    return *(uint32_t*)&h;
}

// ======================= merged prep kernel =======================
// grid 512 x 256:
//   bid [0,128)    : W0x fragment-major image (8 chunks, k<256 of W0)
//   bid [128,256)  : W1 fragment-major image
//   bid [256,512)  : hgf (8 graphs/block) + zero g_norm
__global__ void prep_all_kernel(const float* __restrict__ W0,
                                const float* __restrict__ W1,
                                const float* __restrict__ gf,
                                uint32_t* __restrict__ dW0,
                                uint32_t* __restrict__ dW1) {
    int bid = blockIdx.x;
    int tidl = threadIdx.x;
    if (bid < 256) {
        const float* W = (bid < 128) ? W0 : W1;
        uint32_t* dst  = (bid < 128) ? dW0 : dW1;
        int idx = (bid & 127) * 256 + tidl;
        int c    = idx >> 12;
        int ks   = (idx >> 11) & 1;
        int nw   = (idx >> 9) & 3;
        int jp   = (idx >> 7) & 3;
        int lane = (idx >> 2) & 31;
        int r    = idx & 3;
        int j = jp * 2 + (r >> 1);
        int n = nw * 64 + j * 8 + (lane >> 2);
        int kg = c * 32 + ks * 16 + 2 * (lane & 3) + 8 * (r & 1);
        uint32_t lo = __half_as_ushort(__float2half(W[(size_t)kg * 256 + n]));
        uint32_t hi = __half_as_ushort(__float2half(W[(size_t)(kg + 1) * 256 + n]));
        dst[idx] = lo | (hi << 16);
    } else {
        __shared__ float sg[8][DG];
        int n = tidl;
        int g0 = (bid - 256) * 8;
        if (n < 8) g_norm[g0 + n] = 0.0f;
        for (int i = n; i < 8 * DG; i += 256)
            sg[i >> 7][i & 127] = gf[(size_t)g0 * DG + i];
        __syncthreads();
        float acc[8] = {0.f, 0.f, 0.f, 0.f, 0.f, 0.f, 0.f, 0.f};
        #pragma unroll
        for (int kb = 0; kb < DG; kb += 16) {
            float w[16];
            #pragma unroll
            for (int u = 0; u < 16; u++)
                w[u] = W0[(size_t)(DX + kb + u) * HID + n];   // 16 independent LDGs
            #pragma unroll
            for (int u = 0; u < 16; u++) {
                #pragma unroll
                for (int p = 0; p < 8; p++)
                    acc[p] = fmaf(sg[p][kb + u], w[u], acc[p]);
            }
        }
        #pragma unroll
        for (int p = 0; p < 8; p++) gHGF[(size_t)(g0 + p) * HID + n] = acc[p];
    }
}

__global__ void norm_kernel(const int* __restrict__ bidx, float* __restrict__ out) {
    int i = blockIdx.x * 256 + threadIdx.x;
    out[i] = out[i] / g_norm[bidx[i]];
}

// ======================= device sub-steps =======================
// cp.async one 16KB fragment-major weight chunk g into ring slot g%3
// g 0..7 -> gW0 chunk g ; g 8..15 -> gW1 chunk g-8
__device__ __forceinline__ void issueB(uint32_t sb, int g, int tid) {
    const uint16_t* src = (g < 8) ? (gW0 + g * 8192) : (gW1 + (g - 8) * 8192);
    uint32_t d = sb + (uint32_t)(g % 3) * 16384u;
    #pragma unroll
    for (int i = tid; i < 1024; i += NTHR)
        cp16(d + i * 16, (const char*)src + i * 16);
}

// register-pipelined A chunk load: 64 rows x 32 k fp32 (x only)
__device__ __forceinline__ void ldgA(int c, const float* x, int row0, int tid,
                                     float4& f0, float4& f1) {
    int r = tid >> 2, q = tid & 3;
    const float* src = x + (size_t)(row0 + r) * DX + c * 32 + q * 8;
    f0 = *(const float4*)src;
    f1 = *((const float4*)src + 1);
}

// fp16-convert 8 floats -> single STS.128 into A buf p (144B rows, no XOR)
__device__ __forceinline__ void stsA(char* smc, int p, float4 f0, float4 f1, int tid) {
    int r = tid >> 2, q = tid & 3;
    uint32_t off = ABUF + (uint32_t)p * 9216u + (uint32_t)(r * 144 + q * 16);
    *(uint4*)(smc + off) = make_uint4(pack2h(f0.x, f0.y), pack2h(f0.z, f0.w),
                                      pack2h(f1.x, f1.y), pack2h(f1.z, f1.w));
}

// ======================= main fused kernel (R14 structure) =======================
__global__ __launch_bounds__(NTHR, 2) void att_kernel(
    const float* __restrict__ x, const int* __restrict__ bidx,
    const float* __restrict__ b0,
    const float* __restrict__ W2, const float* __restrict__ b2,
    const float* __restrict__ gamma0, const float* __restrict__ beta0,
    const float* __restrict__ mean0, const float* __restrict__ var0,
    const float* __restrict__ b1,
    const float* __restrict__ gamma1, const float* __restrict__ beta1,
    const float* __restrict__ mean1, const float* __restrict__ var1,
    float* __restrict__ out)
{
    extern __shared__ char smc[];
    const uint32_t sb = smem_u32(smc);
    const int tid = threadIdx.x;
    const int wid = tid >> 5;
    const int lane = tid & 31;
    const int row0 = blockIdx.x * MTILE;
    const int mw = wid >> 2;          // 0..1  M groups of 32
    const int nw = wid & 3;           // 0..3  N groups of 64
    const int qr = lane >> 2;         // 0..7
    const int l15 = lane & 15;
    const int lk  = (lane >> 4) << 4;

    int* sidx = (int*)(smc + SIDX);
    if (tid < MTILE) sidx[tid] = bidx[row0 + tid];
    {   // fold BN params (256 threads = 256 cols)
        int cc = tid;
        float s0v = gamma0[cc] * rsqrtf(var0[cc] + BN_EPS);
        ((float*)(smc + P_S0))[cc]  = s0v;
        ((float*)(smc + P_SH0))[cc] = fmaf(b0[cc] - mean0[cc], s0v, beta0[cc]);
        float s1v = gamma1[cc] * rsqrtf(var1[cc] + BN_EPS);
        ((float*)(smc + P_S1))[cc]  = s1v;
        ((float*)(smc + P_SH1))[cc] = fmaf(b1[cc] - mean1[cc], s1v, beta1[cc]);
        ((float*)(smc + P_W2))[cc]  = W2[cc];
    }

    // prologue: stage W0 c0+c1 (2 groups), convert A(0)
    issueB(sb, 0, tid); CP_COMMIT();
    issueB(sb, 1, tid); CP_COMMIT();
    {
        float4 f0, f1;
        ldgA(0, x, row0, tid, f0, f1);
        stsA(smc, 0, f0, f1, tid);
    }

    float C[2][8][4];
    #pragma unroll
    for (int m = 0; m < 2; m++)
        #pragma unroll
        for (int j = 0; j < 8; j++)
            #pragma unroll
            for (int p = 0; p < 4; p++) C[m][j][p] = 0.0f;

    const uint32_t bfrag = (uint32_t)(nw * 2048 + lane * 16);

    // =================== GEMM1: [64 x 256] @ W0x (8 x 32k chunks) ===================
    for (int i = 0; i < 8; i++) {
        CP_WAIT1();          // B(i) landed (B(i+1) may still be in flight)
        __syncthreads();     // B(i) + A(i) visible; slot (i+2)%3 reads complete
        issueB(sb, i + 2, tid);     // ring: tail issues W1 c0/c1 (g=8,9)
        CP_COMMIT();

        float4 fA0, fA1;
        if (i + 1 < 8) ldgA(i + 1, x, row0, tid, fA0, fA1);

        {   // MMA(i): B slot i%3, abuf i&1
            const uint32_t bsoff = (uint32_t)(i % 3) * 16384u;
            const uint32_t ab = sb + ABUF + (uint32_t)(i & 1) * 9216u;
            #pragma unroll
            for (int ks = 0; ks < 2; ks++) {
                uint32_t a[2][4];
                #pragma unroll
                for (int m = 0; m < 2; m++)
                    ldsm4(a[m], ab + (uint32_t)((mw * 32 + m * 16 + l15) * 144 + ks * 32) + lk);
                #pragma unroll
                for (int jp = 0; jp < 4; jp++) {
                    uint4 bv = *(const uint4*)(smc + bsoff + ks * 8192 + bfrag + jp * 512);
                    mma16816h(C[0][jp * 2],     a[0], bv.x, bv.y);
                    mma16816h(C[0][jp * 2 + 1], a[0], bv.z, bv.w);
                    mma16816h(C[1][jp * 2],     a[1], bv.x, bv.y);
                    mma16816h(C[1][jp * 2 + 1], a[1], bv.z, bv.w);
                }
            }
        }

        if (i + 1 < 8) stsA(smc, (i + 1) & 1, fA0, fA1, tid);
    }
    __syncthreads();     // all ABUF ldsm reads done before h1 overwrites the region

    // ====== Epilogue 1: add per-graph hgf, BN0+ReLU, fp16 convert, write h1 ======
    {
        const float* sS0  = (const float*)(smc + P_S0);
        const float* sSH0 = (const float*)(smc + P_SH0);
        #pragma unroll
        for (int m = 0; m < 2; m++) {
            int r = mw * 32 + m * 16 + qr;
            const float2* hgA = (const float2*)(gHGF + (size_t)sidx[r] * HID);
            const float2* hgB = (const float2*)(gHGF + (size_t)sidx[r + 8] * HID);
            uint32_t xr0 = (uint32_t)(qr << 4);
            uint32_t rb0 = (uint32_t)(r * 512);
            uint32_t rb1 = (uint32_t)((r + 8) * 512);
            #pragma unroll
            for (int j = 0; j < 8; j++) {
                int col = nw * 64 + j * 8 + (lane & 3) * 2;
                float2 ha = hgA[col >> 1];
                float2 hb = hgB[col >> 1];
                float s0a = sS0[col], s0b = sS0[col + 1];
                float h0a = sSH0[col], h0b = sSH0[col + 1];
                float v00 = fmaxf(fmaf(C[m][j][0] + ha.x, s0a, h0a), 0.f);
                float v01 = fmaxf(fmaf(C[m][j][1] + ha.y, s0b, h0b), 0.f);
                float v10 = fmaxf(fmaf(C[m][j][2] + hb.x, s0a, h0a), 0.f);
                float v11 = fmaxf(fmaf(C[m][j][3] + hb.y, s0b, h0b), 0.f);
                uint32_t ko = ((uint32_t)(col * 2)) ^ xr0;
                *(uint32_t*)(smc + H1 + rb0 + ko) = pack2h(v00, v01);
                *(uint32_t*)(smc + H1 + rb1 + ko) = pack2h(v10, v11);
            }
        }
    }

    #pragma unroll
    for (int m = 0; m < 2; m++)
        #pragma unroll
        for (int j = 0; j < 8; j++)
            #pragma unroll
            for (int p = 0; p < 4; p++) C[m][j][p] = 0.0f;

    // =================== GEMM2: h1 [64 x 256] @ W1 (8 x 32k chunks) ===================
    for (int i = 0; i < 8; i++) {
        const int g = 8 + i;
        // Last chunk: nothing newer in flight -> must drain fully.
        if (i == 7) { CP_WAIT0(); } else { CP_WAIT1(); }
        __syncthreads();     // h1 (i=0) / slot reuse + B visibility
        if (g + 2 <= 15) { issueB(sb, g + 2, tid); CP_COMMIT(); }

        {   // MMA: B slot g%3, A from h1 (ldmatrix, 16B-XOR layout)
            const uint32_t bsoff = (uint32_t)(g % 3) * 16384u;
            #pragma unroll
            for (int ks = 0; ks < 2; ks++) {
                uint32_t a[2][4];
                #pragma unroll
                for (int m = 0; m < 2; m++) {
                    int row = mw * 32 + m * 16 + l15;
                    uint32_t kb = (uint32_t)(i * 64 + ks * 32) + (uint32_t)lk;
                    ldsm4(a[m], sb + H1 + (uint32_t)(row * 512) +
                                 (kb ^ ((uint32_t)(row & 7) << 4)));
                }
                #pragma unroll
                for (int jp = 0; jp < 4; jp++) {
                    uint4 bv = *(const uint4*)(smc + bsoff + ks * 8192 + bfrag + jp * 512);
                    mma16816h(C[0][jp * 2],     a[0], bv.x, bv.y);
                    mma16816h(C[0][jp * 2 + 1], a[0], bv.z, bv.w);
                    mma16816h(C[1][jp * 2],     a[1], bv.x, bv.y);
                    mma16816h(C[1][jp * 2 + 1], a[1], bv.z, bv.w);
                }
            }
        }
    }

    // ====== Epilogue 2: BN1+ReLU, dot W2, reduce, exp, segment atomics ======
    {
        const float* sS1  = (const float*)(smc + P_S1);
        const float* sSH1 = (const float*)(smc + P_SH1);
        const float* sW2  = (const float*)(smc + P_W2);
        float pl[2][2] = {{0.f, 0.f}, {0.f, 0.f}};
        #pragma unroll
        for (int m = 0; m < 2; m++) {
            #pragma unroll
            for (int j = 0; j < 8; j++) {
                int col = nw * 64 + j * 8 + (lane & 3) * 2;
                float s1a = sS1[col], s1b = sS1[col + 1];
                float h1a = sSH1[col], h1b = sSH1[col + 1];
                float w2a = sW2[col], w2b = sW2[col + 1];
                pl[m][0] = fmaf(fmaxf(fmaf(C[m][j][0], s1a, h1a), 0.f), w2a, pl[m][0]);
                pl[m][0] = fmaf(fmaxf(fmaf(C[m][j][1], s1b, h1b), 0.f), w2b, pl[m][0]);
                pl[m][1] = fmaf(fmaxf(fmaf(C[m][j][2], s1a, h1a), 0.f), w2a, pl[m][1]);
                pl[m][1] = fmaf(fmaxf(fmaf(C[m][j][3], s1b, h1b), 0.f), w2b, pl[m][1]);
            }
        }
        #pragma unroll
        for (int off = 1; off <= 2; off <<= 1)
            #pragma unroll
            for (int m = 0; m < 2; m++) {
                pl[m][0] += __shfl_xor_sync(0xffffffffu, pl[m][0], off);
                pl[m][1] += __shfl_xor_sync(0xffffffffu, pl[m][1], off);
            }
        float* part = (float*)(smc + PART);
        if ((lane & 3) == 0) {
            #pragma unroll
            for (int m = 0; m < 2; m++) {
                int r = mw * 32 + m * 16 + qr;
                part[nw * 64 + r]     = pl[m][0];
                part[nw * 64 + r + 8] = pl[m][1];
            }
        }
        __syncthreads();
        if (tid < MTILE) {
            float logit = part[tid] + part[64 + tid] + part[128 + tid] +
                          part[192 + tid] + b2[0];
            float av = expf(logit);
            out[row0 + tid] = av;
            atomicAdd(&g_norm[sidx[tid]], av);
        }
    }
}

// ======================= launch =======================
extern "C" void kernel_launch(void* const* d_in, const int* in_sizes, int n_in,
                              void* d_out, int out_size) {
    const float* x      = (const float*)d_in[0];
    const int*   bidx   = (const int*)  d_in[1];
    const float* gf     = (const float*)d_in[2];
    const float* W0     = (const float*)d_in[3];
    const float* b0     = (const float*)d_in[4];
    const float* W1     = (const float*)d_in[5];
    const float* b1     = (const float*)d_in[6];
    const float* W2     = (const float*)d_in[7];
    const float* b2     = (const float*)d_in[8];
    const float* gamma0 = (const float*)d_in[9];
    const float* beta0  = (const float*)d_in[10];
    const float* mean0  = (const float*)d_in[11];
    const float* var0   = (const float*)d_in[12];
    const float* gamma1 = (const float*)d_in[13];
    const float* beta1  = (const float*)d_in[14];
    const float* mean1  = (const float*)d_in[15];
    const float* var1   = (const float*)d_in[16];
    float* out = (float*)d_out;

    static uint32_t *pW0 = nullptr, *pW1;
    if (!pW0) {
        cudaGetSymbolAddress((void**)&pW0, gW0);
        cudaGetSymbolAddress((void**)&pW1, gW1);
        cudaFuncSetAttribute(att_kernel, cudaFuncAttributeMaxDynamicSharedMemorySize,
                             SMEM_TOTAL);
    }

    prep_all_kernel<<<512, 256>>>(W0, W1, gf, pW0, pW1);
    att_kernel<<<NCTA, NTHR, SMEM_TOTAL>>>(
        x, bidx, b0, W2, b2,
        gamma0, beta0, mean0, var0,
        b1, gamma1, beta1, mean1, var1, out);
    norm_kernel<<<NN / 256, 256>>>(bidx, out);
}